// round 6
// baseline (speedup 1.0000x reference)
#include <cuda_runtime.h>
#include <math.h>
#include <float.h>

#define B_ 2
#define L_ 2048
#define E_ 1024
#define H_ 16
#define DK_ 64
#define DV_ 64
#define TOPK_ 64
#define NROWS_ (B_*H_*L_)   /* 65536 */

typedef unsigned long long u64;

// ---------------- device scratch (no allocations allowed) ----------------
__device__ float g_qp[(size_t)B_*H_*L_*DK_];      // [b][h][l][d] 16MB
__device__ float g_kp[(size_t)B_*H_*L_*DK_];      // 16MB
__device__ float g_vp[(size_t)B_*H_*L_*DV_];      // 16MB
__device__ float g_mixed[(size_t)B_*L_*H_*DV_];   // [b][l][h*64+d] 16MB
__device__ int   g_ti[(size_t)NROWS_*TOPK_];      // top-k indices
__device__ float g_tp[(size_t)NROWS_*TOPK_];      // top-k probs
__device__ float g_lscratch[(size_t)L_*L_];       // per-(b,h) logits fallback, 16MB

// ---------------- packed f32x2 helpers ----------------
__device__ __forceinline__ u64 dup2(float x) {
    unsigned u = __float_as_uint(x);
    u64 r; asm("mov.b64 %0, {%1, %1};" : "=l"(r) : "r"(u)); return r;
}
__device__ __forceinline__ void unpk2(u64 v, float& lo, float& hi) {
    unsigned a, b; asm("mov.b64 {%0, %1}, %2;" : "=r"(a), "=r"(b) : "l"(v));
    lo = __uint_as_float(a); hi = __uint_as_float(b);
}
__device__ __forceinline__ u64 f2add(u64 a, u64 b) {
    u64 d; asm("add.rn.f32x2 %0, %1, %2;" : "=l"(d) : "l"(a), "l"(b)); return d;
}
__device__ __forceinline__ u64 f2mul(u64 a, u64 b) {
    u64 d; asm("mul.rn.f32x2 %0, %1, %2;" : "=l"(d) : "l"(a), "l"(b)); return d;
}
__device__ __forceinline__ void f2fma(u64& d, u64 a, u64 b) {
    asm("fma.rn.f32x2 %0, %1, %2, %3;" : "=l"(d) : "l"(a), "l"(b), "l"(d));
}
#define SGN2 0x8000000080000000ULL

// Knuth TwoSum (branch-free, exact) in packed f32x2: tot/comp accumulate chunk c
__device__ __forceinline__ void ksum2(u64& tot, u64& comp, u64 c) {
    u64 s  = f2add(tot, c);
    u64 bv = f2add(s, tot ^ SGN2);   // s - tot
    u64 av = f2add(s, bv  ^ SGN2);   // s - bv
    u64 ar = f2add(tot, av ^ SGN2);  // tot - av
    u64 br = f2add(c,   bv ^ SGN2);  // c - bv
    comp = f2add(comp, f2add(ar, br));
    tot = s;
}

// ---------------- merged projection SGEMM (compensated, packed) ----------------
__global__ __launch_bounds__(256, 2) void proj_kernel(
    const float* __restrict__ q, const float* __restrict__ k, const float* __restrict__ v,
    const float* __restrict__ w_qs, const float* __restrict__ w_ks, const float* __restrict__ w_vs)
{
    __shared__ float As[16][128];   // [k][m]
    __shared__ float Bs[16][64];    // [k][n]
    const int z = blockIdx.z;
    const float* __restrict__ A = (z == 0) ? q : (z == 1) ? k : v;
    const float* __restrict__ W = (z == 0) ? w_qs : (z == 1) ? w_ks : w_vs;
    float* __restrict__ P = (z == 0) ? g_qp : (z == 1) ? g_kp : g_vp;
    const int K = (z == 2) ? DV_ : E_;

    const int tid = threadIdx.x;
    const int m0 = blockIdx.y * 128, n0 = blockIdx.x * 64;
    const int tx = tid & 15, ty = tid >> 4;
    u64 tot[4][4] = {}, comp[4][4] = {};

    for (int k0 = 0; k0 < K; k0 += 16) {
        #pragma unroll
        for (int it = 0; it < 2; it++) {
            int idx = (it << 8) + tid;
            int r = idx >> 2, c = (idx & 3) << 2;
            const float4 a4 = *(const float4*)(A + (size_t)(m0 + r) * K + (k0 + c));
            As[c+0][r] = a4.x; As[c+1][r] = a4.y; As[c+2][r] = a4.z; As[c+3][r] = a4.w;
        }
        {
            int r = tid >> 4, c = (tid & 15) << 2;
            *(float4*)&Bs[r][c] = *(const float4*)(W + (size_t)(k0 + r) * (H_*DK_) + n0 + c);
        }
        __syncthreads();

        u64 cacc[4][4] = {};
        #pragma unroll
        for (int kk = 0; kk < 16; kk++) {
            const ulonglong2* ap = (const ulonglong2*)&As[kk][ty*8];
            ulonglong2 p0 = ap[0], p1 = ap[1];
            u64 a0 = p0.x, a1 = p0.y, a2 = p1.x, a3 = p1.y;
            float4 b4 = *(const float4*)&Bs[kk][tx*4];
            u64 b0 = dup2(b4.x), b1 = dup2(b4.y), b2 = dup2(b4.z), b3 = dup2(b4.w);
            f2fma(cacc[0][0], a0, b0); f2fma(cacc[0][1], a0, b1); f2fma(cacc[0][2], a0, b2); f2fma(cacc[0][3], a0, b3);
            f2fma(cacc[1][0], a1, b0); f2fma(cacc[1][1], a1, b1); f2fma(cacc[1][2], a1, b2); f2fma(cacc[1][3], a1, b3);
            f2fma(cacc[2][0], a2, b0); f2fma(cacc[2][1], a2, b1); f2fma(cacc[2][2], a2, b2); f2fma(cacc[2][3], a2, b3);
            f2fma(cacc[3][0], a3, b0); f2fma(cacc[3][1], a3, b1); f2fma(cacc[3][2], a3, b2); f2fma(cacc[3][3], a3, b3);
        }
        #pragma unroll
        for (int i = 0; i < 4; i++)
            #pragma unroll
            for (int j = 0; j < 4; j++)
                ksum2(tot[i][j], comp[i][j], cacc[i][j]);
        __syncthreads();
    }

    #pragma unroll
    for (int i = 0; i < 4; i++) {
        int me = m0 + ty*8 + 2*i;
        int be = me >> 11, le = me & (L_-1);
        #pragma unroll
        for (int j = 0; j < 4; j++) {
            int n = n0 + tx*4 + j;
            int h = n >> 6, d = n & 63;
            u64 r = f2add(tot[i][j], comp[i][j]);
            float lo, hi; unpk2(r, lo, hi);
            P[((((size_t)be*H_ + h)*L_ + le)       << 6) + d] = lo;
            P[((((size_t)be*H_ + h)*L_ + (le + 1)) << 6) + d] = hi;
        }
    }
}

// ---------------- logits (compensated, packed): per (b,h): scale * QP @ KP^T ----------------
__global__ __launch_bounds__(256, 2) void logits_kernel(float* __restrict__ dst_arg, int bh0, int full)
{
    __shared__ float Qs[16][128];   // [k][m]
    __shared__ float Ks[16][64];    // [k][n]
    const int tid = threadIdx.x;
    const int bh = bh0 + blockIdx.z;
    const float* __restrict__ qp = g_qp + (size_t)bh * L_ * DK_;
    const float* __restrict__ kp = g_kp + (size_t)bh * L_ * DK_;
    const int m0 = blockIdx.y * 128, n0 = blockIdx.x * 64;
    const int tx = tid & 15, ty = tid >> 4;
    u64 tot[4][4] = {}, comp[4][4] = {};

    for (int k0 = 0; k0 < DK_; k0 += 16) {
        #pragma unroll
        for (int it = 0; it < 2; it++) {
            int idx = (it << 8) + tid;
            int r = idx >> 2, c = (idx & 3) << 2;
            const float4 a4 = *(const float4*)(qp + (size_t)(m0 + r) * DK_ + k0 + c);
            Qs[c+0][r] = a4.x; Qs[c+1][r] = a4.y; Qs[c+2][r] = a4.z; Qs[c+3][r] = a4.w;
        }
        {
            int r = tid >> 2, c = (tid & 3) << 2;   // r: n-row 0..63, c: k-offset
            const float4 b4 = *(const float4*)(kp + (size_t)(n0 + r) * DK_ + k0 + c);
            Ks[c+0][r] = b4.x; Ks[c+1][r] = b4.y; Ks[c+2][r] = b4.z; Ks[c+3][r] = b4.w;
        }
        __syncthreads();

        u64 cacc[4][4] = {};
        #pragma unroll
        for (int kk = 0; kk < 16; kk++) {
            const ulonglong2* ap = (const ulonglong2*)&Qs[kk][ty*8];
            ulonglong2 p0 = ap[0], p1 = ap[1];
            u64 a0 = p0.x, a1 = p0.y, a2 = p1.x, a3 = p1.y;
            float4 b4 = *(const float4*)&Ks[kk][tx*4];
            u64 b0 = dup2(b4.x), b1 = dup2(b4.y), b2 = dup2(b4.z), b3 = dup2(b4.w);
            f2fma(cacc[0][0], a0, b0); f2fma(cacc[0][1], a0, b1); f2fma(cacc[0][2], a0, b2); f2fma(cacc[0][3], a0, b3);
            f2fma(cacc[1][0], a1, b0); f2fma(cacc[1][1], a1, b1); f2fma(cacc[1][2], a1, b2); f2fma(cacc[1][3], a1, b3);
            f2fma(cacc[2][0], a2, b0); f2fma(cacc[2][1], a2, b1); f2fma(cacc[2][2], a2, b2); f2fma(cacc[2][3], a2, b3);
            f2fma(cacc[3][0], a3, b0); f2fma(cacc[3][1], a3, b1); f2fma(cacc[3][2], a3, b2); f2fma(cacc[3][3], a3, b3);
        }
        #pragma unroll
        for (int i = 0; i < 4; i++)
            #pragma unroll
            for (int j = 0; j < 4; j++)
                ksum2(tot[i][j], comp[i][j], cacc[i][j]);
        __syncthreads();
    }

    const u64 MULT2 = 0x3E2000003E200000ULL;  // (0.15625f, 0.15625f) exact
    float* __restrict__ dst = full ? dst_arg : g_lscratch;
    size_t base = full ? ((size_t)bh * L_ * L_) : 0;
    float res[8][4];
    #pragma unroll
    for (int i = 0; i < 4; i++)
        #pragma unroll
        for (int j = 0; j < 4; j++) {
            u64 r = f2mul(f2add(tot[i][j], comp[i][j]), MULT2);
            unpk2(r, res[2*i][j], res[2*i+1][j]);
        }
    #pragma unroll
    for (int i = 0; i < 8; i++) {
        int m = m0 + ty*8 + i;
        float* rp = dst + base + (size_t)m * L_ + n0 + tx*4;
        *(float4*)rp = make_float4(res[i][0], res[i][1], res[i][2], res[i][3]);
    }
}

// ---------------- top-k v3: 1 histogram pass + candidate refinement (exact) ----------------
__device__ __forceinline__ unsigned fkey(float f) {
    unsigned u = __float_as_uint(f);
    return (u & 0x80000000u) ? ~u : (u | 0x80000000u);  // order-preserving
}

// inclusive suffix scan over nb bins held as hist[]; returns selected bin + inner rem via s_sel/s_rem
__device__ __forceinline__ void suffix_select(
    unsigned* hist, int nb, int rem,
    unsigned* wpart, unsigned& s_sel_ref, unsigned& s_rem_ref,
    int tid, int lane, int wid)
{
    const int bpt = nb >> 8;
    unsigned bsuf[8];
    unsigned tsum = 0;
    for (int j = bpt - 1; j >= 0; j--) { tsum += hist[tid*bpt + j]; bsuf[j] = tsum; }
    unsigned wsuf = tsum;
    #pragma unroll
    for (int off = 1; off < 32; off <<= 1) {
        unsigned o = __shfl_down_sync(0xffffffffu, wsuf, off);
        if (lane + off < 32) wsuf += o;
    }
    if (lane == 0) wpart[wid] = wsuf;
    __syncthreads();
    unsigned above = wsuf - tsum;
    for (int w = wid + 1; w < 8; w++) above += wpart[w];
    for (int j = 0; j < bpt; j++) {
        unsigned Si = above + bsuf[j];
        unsigned own = bsuf[j] - ((j + 1 < bpt) ? bsuf[j+1] : 0u);
        unsigned Se = Si - own;
        if ((int)Si >= rem && (int)Se < rem) {
            s_sel_ref = (unsigned)(tid*bpt + j);
            s_rem_ref = (unsigned)(rem - (int)Se);
        }
    }
    __syncthreads();
}

__global__ __launch_bounds__(256) void topk_softmax_kernel(
    float* __restrict__ src_arg, int row0, int write_attn)
{
    __shared__ float row[L_];
    __shared__ unsigned hist[2048];
    __shared__ unsigned cand[2048];
    __shared__ unsigned wpart[8];
    __shared__ float redf[8];
    __shared__ unsigned s_sel, s_rem;
    __shared__ float s_mx, s_inv;
    __shared__ int s_cnt, s_ccnt;

    const int tid = threadIdx.x, lane = tid & 31, wid = tid >> 5;
    float* __restrict__ base = write_attn ? src_arg : g_lscratch;
    float* __restrict__ rptr = base + (size_t)blockIdx.x * L_;
    const int row_id = row0 + blockIdx.x;

    // zero histogram first, then fused load + max + 11-bit histogram
    #pragma unroll
    for (int j = 0; j < 8; j++) hist[tid + (j << 8)] = 0;
    if (tid == 0) { s_cnt = 0; s_ccnt = 0; }
    __syncthreads();

    float mx = -FLT_MAX;
    #pragma unroll
    for (int i = 0; i < 2; i++) {
        float4 v4 = ((const float4*)rptr)[tid + (i << 8)];
        ((float4*)row)[tid + (i << 8)] = v4;
        mx = fmaxf(fmaxf(fmaxf(mx, v4.x), v4.y), fmaxf(v4.z, v4.w));
        atomicAdd(&hist[fkey(v4.x) >> 21], 1u);
        atomicAdd(&hist[fkey(v4.y) >> 21], 1u);
        atomicAdd(&hist[fkey(v4.z) >> 21], 1u);
        atomicAdd(&hist[fkey(v4.w) >> 21], 1u);
    }
    #pragma unroll
    for (int off = 16; off > 0; off >>= 1) mx = fmaxf(mx, __shfl_xor_sync(0xffffffffu, mx, off));
    if (lane == 0) redf[wid] = mx;
    __syncthreads();
    if (tid == 0) {
        float m2 = redf[0];
        #pragma unroll
        for (int w = 1; w < 8; w++) m2 = fmaxf(m2, redf[w]);
        s_mx = m2;
    }

    // pass 1 selection over top 11 bits
    suffix_select(hist, 2048, TOPK_, wpart, s_sel, s_rem, tid, lane, wid);
    const unsigned b1 = s_sel;
    int rem = (int)s_rem;
    __syncthreads();

    // gather candidates from selected bin
    #pragma unroll
    for (int i = 0; i < 8; i++) {
        unsigned key = fkey(row[tid + (i << 8)]);
        if ((key >> 21) == b1) {
            int pos = atomicAdd(&s_ccnt, 1);
            cand[pos] = key;
        }
    }
    __syncthreads();
    const int c = s_ccnt;

    // refinement pass A: bits [10:21) of candidates (2048 bins)
    #pragma unroll
    for (int j = 0; j < 8; j++) hist[tid + (j << 8)] = 0;
    __syncthreads();
    for (int j = tid; j < c; j += 256)
        atomicAdd(&hist[(cand[j] >> 10) & 2047u], 1u);
    __syncthreads();
    suffix_select(hist, 2048, rem, wpart, s_sel, s_rem, tid, lane, wid);
    const unsigned sel0 = s_sel;
    rem = (int)s_rem;
    __syncthreads();

    // refinement pass B: bits [0:10) (1024 bins)
    #pragma unroll
    for (int j = 0; j < 4; j++) hist[tid + (j << 8)] = 0;
    __syncthreads();
    for (int j = tid; j < c; j += 256) {
        unsigned key = cand[j];
        if (((key >> 10) & 2047u) == sel0)
            atomicAdd(&hist[key & 1023u], 1u);
    }
    __syncthreads();
    suffix_select(hist, 1024, rem, wpart, s_sel, s_rem, tid, lane, wid);
    const unsigned kth = (b1 << 21) | (sel0 << 10) | s_sel;  // exact 64th-largest key
    const float mxv = s_mx;
    __syncthreads();

    // exp over kept + sum
    float sm = 0.f;
    #pragma unroll
    for (int i = 0; i < 8; i++) {
        int idx = tid + (i << 8);
        float l = row[idx];
        float e = 0.f;
        if (fkey(l) >= kth) e = expf(l - mxv);
        row[idx] = e;
        sm += e;
    }
    #pragma unroll
    for (int off = 16; off > 0; off >>= 1) sm += __shfl_xor_sync(0xffffffffu, sm, off);
    if (lane == 0) redf[wid] = sm;
    __syncthreads();
    if (tid == 0) {
        float s2 = 0.f;
        #pragma unroll
        for (int w = 0; w < 8; w++) s2 += redf[w];
        s_inv = 1.f / s2;
    }
    __syncthreads();
    const float inv = s_inv;

    // write attn row (streaming) + compact (idx, p) pairs for sparse PV
    #pragma unroll
    for (int i = 0; i < 2; i++) {
        int vidx = tid + (i << 8);
        float4 e4 = ((float4*)row)[vidx];
        float4 p4 = make_float4(e4.x*inv, e4.y*inv, e4.z*inv, e4.w*inv);
        if (write_attn) __stcs(((float4*)rptr) + vidx, p4);
        int bidx = vidx << 2;
        if (e4.x > 0.f) { int pos = atomicAdd(&s_cnt, 1); if (pos < TOPK_) { g_ti[(size_t)row_id*TOPK_+pos] = bidx+0; g_tp[(size_t)row_id*TOPK_+pos] = p4.x; } }
        if (e4.y > 0.f) { int pos = atomicAdd(&s_cnt, 1); if (pos < TOPK_) { g_ti[(size_t)row_id*TOPK_+pos] = bidx+1; g_tp[(size_t)row_id*TOPK_+pos] = p4.y; } }
        if (e4.z > 0.f) { int pos = atomicAdd(&s_cnt, 1); if (pos < TOPK_) { g_ti[(size_t)row_id*TOPK_+pos] = bidx+2; g_tp[(size_t)row_id*TOPK_+pos] = p4.z; } }
        if (e4.w > 0.f) { int pos = atomicAdd(&s_cnt, 1); if (pos < TOPK_) { g_ti[(size_t)row_id*TOPK_+pos] = bidx+3; g_tp[(size_t)row_id*TOPK_+pos] = p4.w; } }
    }
}

// ---------------- sparse PV: mixed[b][l][h*64+d] = sum over 64 kept keys ----------------
__global__ __launch_bounds__(256) void pv_kernel()
{
    const int row  = blockIdx.x * 8 + (threadIdx.x >> 5);
    const int lane = threadIdx.x & 31;
    const int bh = row >> 11, qi = row & (L_-1);
    const float* __restrict__ vp = g_vp + (size_t)bh * L_ * DV_;
    const int*   __restrict__ ti = g_ti + (size_t)row * TOPK_;
    const float* __restrict__ tp = g_tp + (size_t)row * TOPK_;

    float a0 = 0.f, a1 = 0.f;
    int   i1 = ti[lane];      float p1 = tp[lane];
    int   i2 = ti[32 + lane]; float p2 = tp[32 + lane];
    #pragma unroll
    for (int t = 0; t < 32; t++) {
        int idx = __shfl_sync(0xffffffffu, i1, t);
        float p = __shfl_sync(0xffffffffu, p1, t);
        const float* vr = vp + (size_t)idx * DV_;
        a0 = fmaf(p, vr[lane],      a0);
        a1 = fmaf(p, vr[32 + lane], a1);
    }
    #pragma unroll
    for (int t = 0; t < 32; t++) {
        int idx = __shfl_sync(0xffffffffu, i2, t);
        float p = __shfl_sync(0xffffffffu, p2, t);
        const float* vr = vp + (size_t)idx * DV_;
        a0 = fmaf(p, vr[lane],      a0);
        a1 = fmaf(p, vr[32 + lane], a1);
    }
    const int b = bh >> 4, h = bh & (H_-1);
    float* md = g_mixed + ((size_t)(b * L_ + qi) * (H_*DV_)) + h * DV_;
    md[lane]      = a0;
    md[32 + lane] = a1;
}

// ---------------- fc: out[b*L+l][o] = mixed[row] . fc[:,o] ----------------
__global__ __launch_bounds__(256) void fc_kernel(const float* __restrict__ fcw, float* __restrict__ out)
{
    __shared__ float ms[8][E_];
    const int tid = threadIdx.x;
    const int row0 = blockIdx.x * 8;
    #pragma unroll
    for (int i = 0; i < 8; i++) {
        int idx = (i << 8) + tid;
        ((float4*)&ms[0][0])[idx] = ((const float4*)(g_mixed + (size_t)row0 * E_))[idx];
    }
    __syncthreads();
    const int o = tid & 63, q = tid >> 6;
    float acc0 = 0.f, acc1 = 0.f;
    #pragma unroll 4
    for (int c0 = 0; c0 < E_; c0 += 4) {
        float4 m0 = *(const float4*)&ms[q][c0];
        float4 m1 = *(const float4*)&ms[q + 4][c0];
        float w0 = fcw[(c0+0) * 64 + o];
        float w1 = fcw[(c0+1) * 64 + o];
        float w2 = fcw[(c0+2) * 64 + o];
        float w3 = fcw[(c0+3) * 64 + o];
        acc0 = fmaf(m0.x, w0, acc0); acc0 = fmaf(m0.y, w1, acc0);
        acc0 = fmaf(m0.z, w2, acc0); acc0 = fmaf(m0.w, w3, acc0);
        acc1 = fmaf(m1.x, w0, acc1); acc1 = fmaf(m1.y, w1, acc1);
        acc1 = fmaf(m1.z, w2, acc1); acc1 = fmaf(m1.w, w3, acc1);
    }
    out[(size_t)(row0 + q)     * 64 + o] = acc0;
    out[(size_t)(row0 + q + 4) * 64 + o] = acc1;
}

// ---------------- launcher ----------------
extern "C" void kernel_launch(void* const* d_in, const int* in_sizes, int n_in,
                              void* d_out, int out_size)
{
    const float* q    = (const float*)d_in[0];
    const float* k    = (const float*)d_in[1];
    const float* v    = (const float*)d_in[2];
    const float* w_qs = (const float*)d_in[3];
    const float* w_ks = (const float*)d_in[4];
    const float* w_vs = (const float*)d_in[5];
    const float* fcw  = (const float*)d_in[6];
    float* outp = (float*)d_out;

    const size_t n_out  = (size_t)B_ * L_ * DV_;         // 262144
    const size_t n_attn = (size_t)B_ * H_ * L_ * L_;     // 134217728

    proj_kernel<<<dim3(16, 32, 3), 256>>>(q, k, v, w_qs, w_ks, w_vs);

    bool has_out = false;
    float* attn_ptr = nullptr;
    if ((size_t)out_size == n_out + n_attn) { has_out = true; attn_ptr = outp + n_out; }
    else if ((size_t)out_size == n_attn)    { attn_ptr = outp; }
    else                                    { has_out = true; }

    if (attn_ptr) {
        logits_kernel<<<dim3(32, 16, B_*H_), 256>>>(attn_ptr, 0, 1);
        topk_softmax_kernel<<<NROWS_, 256>>>(attn_ptr, 0, 1);
    } else {
        for (int bh = 0; bh < B_ * H_; bh++) {
            logits_kernel<<<dim3(32, 16, 1), 256>>>(nullptr, bh, 0);
            topk_softmax_kernel<<<L_, 256>>>(nullptr, bh * L_, 0);
        }
    }

    if (has_out) {
        pv_kernel<<<NROWS_/8, 256>>>();
        fc_kernel<<<(B_*L_)/8, 256>>>(fcw, outp);
    }
}

// round 7
// speedup vs baseline: 1.0663x; 1.0663x over previous
#include <cuda_runtime.h>
#include <math.h>
#include <float.h>

#define B_ 2
#define L_ 2048
#define E_ 1024
#define H_ 16
#define DK_ 64
#define DV_ 64
#define TOPK_ 64
#define NROWS_ (B_*H_*L_)   /* 65536 */

typedef unsigned long long u64;

// ---------------- device scratch (no allocations allowed) ----------------
__device__ float g_qp[(size_t)B_*H_*L_*DK_];      // [b][h][l][d] 16MB
__device__ float g_kp[(size_t)B_*H_*L_*DK_];      // 16MB
__device__ float g_vp[(size_t)B_*H_*L_*DV_];      // 16MB
__device__ float g_mixed[(size_t)B_*L_*H_*DV_];   // [b][l][h*64+d] 16MB
__device__ int   g_ti[(size_t)NROWS_*TOPK_];      // top-k indices
__device__ float g_tp[(size_t)NROWS_*TOPK_];      // top-k probs
__device__ float g_lscratch[(size_t)L_*L_];       // per-(b,h) logits fallback, 16MB

// ---------------- packed f32x2 helpers ----------------
__device__ __forceinline__ u64 dup2(float x) {
    unsigned u = __float_as_uint(x);
    u64 r; asm("mov.b64 %0, {%1, %1};" : "=l"(r) : "r"(u)); return r;
}
__device__ __forceinline__ void unpk2(u64 v, float& lo, float& hi) {
    unsigned a, b; asm("mov.b64 {%0, %1}, %2;" : "=r"(a), "=r"(b) : "l"(v));
    lo = __uint_as_float(a); hi = __uint_as_float(b);
}
__device__ __forceinline__ u64 f2add(u64 a, u64 b) {
    u64 d; asm("add.rn.f32x2 %0, %1, %2;" : "=l"(d) : "l"(a), "l"(b)); return d;
}
__device__ __forceinline__ u64 f2mul(u64 a, u64 b) {
    u64 d; asm("mul.rn.f32x2 %0, %1, %2;" : "=l"(d) : "l"(a), "l"(b)); return d;
}
__device__ __forceinline__ void f2fma(u64& d, u64 a, u64 b) {
    asm("fma.rn.f32x2 %0, %1, %2, %3;" : "=l"(d) : "l"(a), "l"(b), "l"(d));
}
#define SGN2 0x8000000080000000ULL

// Knuth TwoSum (branch-free, exact) in packed f32x2: tot/comp accumulate chunk c
__device__ __forceinline__ void ksum2(u64& tot, u64& comp, u64 c) {
    u64 s  = f2add(tot, c);
    u64 bv = f2add(s, tot ^ SGN2);   // s - tot
    u64 av = f2add(s, bv  ^ SGN2);   // s - bv
    u64 ar = f2add(tot, av ^ SGN2);  // tot - av
    u64 br = f2add(c,   bv ^ SGN2);  // c - bv
    comp = f2add(comp, f2add(ar, br));
    tot = s;
}

// ---------------- merged projection SGEMM (compensated, packed) ----------------
__global__ __launch_bounds__(256, 2) void proj_kernel(
    const float* __restrict__ q, const float* __restrict__ k, const float* __restrict__ v,
    const float* __restrict__ w_qs, const float* __restrict__ w_ks, const float* __restrict__ w_vs)
{
    __shared__ float As[16][128];   // [k][m]
    __shared__ float Bs[16][64];    // [k][n]
    const int z = blockIdx.z;
    const float* __restrict__ A = (z == 0) ? q : (z == 1) ? k : v;
    const float* __restrict__ W = (z == 0) ? w_qs : (z == 1) ? w_ks : w_vs;
    float* __restrict__ P = (z == 0) ? g_qp : (z == 1) ? g_kp : g_vp;
    const int K = (z == 2) ? DV_ : E_;

    const int tid = threadIdx.x;
    const int m0 = blockIdx.y * 128, n0 = blockIdx.x * 64;
    const int tx = tid & 15, ty = tid >> 4;
    u64 tot[4][4] = {}, comp[4][4] = {};

    for (int k0 = 0; k0 < K; k0 += 16) {
        #pragma unroll
        for (int it = 0; it < 2; it++) {
            int idx = (it << 8) + tid;
            int r = idx >> 2, c = (idx & 3) << 2;
            const float4 a4 = *(const float4*)(A + (size_t)(m0 + r) * K + (k0 + c));
            As[c+0][r] = a4.x; As[c+1][r] = a4.y; As[c+2][r] = a4.z; As[c+3][r] = a4.w;
        }
        {
            int r = tid >> 4, c = (tid & 15) << 2;
            *(float4*)&Bs[r][c] = *(const float4*)(W + (size_t)(k0 + r) * (H_*DK_) + n0 + c);
        }
        __syncthreads();

        u64 cacc[4][4] = {};
        #pragma unroll
        for (int kk = 0; kk < 16; kk++) {
            const ulonglong2* ap = (const ulonglong2*)&As[kk][ty*8];
            ulonglong2 p0 = ap[0], p1 = ap[1];
            u64 a0 = p0.x, a1 = p0.y, a2 = p1.x, a3 = p1.y;
            float4 b4 = *(const float4*)&Bs[kk][tx*4];
            u64 b0 = dup2(b4.x), b1 = dup2(b4.y), b2 = dup2(b4.z), b3 = dup2(b4.w);
            f2fma(cacc[0][0], a0, b0); f2fma(cacc[0][1], a0, b1); f2fma(cacc[0][2], a0, b2); f2fma(cacc[0][3], a0, b3);
            f2fma(cacc[1][0], a1, b0); f2fma(cacc[1][1], a1, b1); f2fma(cacc[1][2], a1, b2); f2fma(cacc[1][3], a1, b3);
            f2fma(cacc[2][0], a2, b0); f2fma(cacc[2][1], a2, b1); f2fma(cacc[2][2], a2, b2); f2fma(cacc[2][3], a2, b3);
            f2fma(cacc[3][0], a3, b0); f2fma(cacc[3][1], a3, b1); f2fma(cacc[3][2], a3, b2); f2fma(cacc[3][3], a3, b3);
        }
        #pragma unroll
        for (int i = 0; i < 4; i++)
            #pragma unroll
            for (int j = 0; j < 4; j++)
                ksum2(tot[i][j], comp[i][j], cacc[i][j]);
        __syncthreads();
    }

    #pragma unroll
    for (int i = 0; i < 4; i++) {
        int me = m0 + ty*8 + 2*i;
        int be = me >> 11, le = me & (L_-1);
        #pragma unroll
        for (int j = 0; j < 4; j++) {
            int n = n0 + tx*4 + j;
            int h = n >> 6, d = n & 63;
            u64 r = f2add(tot[i][j], comp[i][j]);
            float lo, hi; unpk2(r, lo, hi);
            P[((((size_t)be*H_ + h)*L_ + le)       << 6) + d] = lo;
            P[((((size_t)be*H_ + h)*L_ + (le + 1)) << 6) + d] = hi;
        }
    }
}

// ---------------- logits (compensated, packed): per (b,h): scale * QP @ KP^T ----------------
__global__ __launch_bounds__(256, 2) void logits_kernel(float* __restrict__ dst_arg, int bh0, int full)
{
    __shared__ float Qs[16][128];   // [k][m]
    __shared__ float Ks[16][64];    // [k][n]
    const int tid = threadIdx.x;
    const int bh = bh0 + blockIdx.z;
    const float* __restrict__ qp = g_qp + (size_t)bh * L_ * DK_;
    const float* __restrict__ kp = g_kp + (size_t)bh * L_ * DK_;
    const int m0 = blockIdx.y * 128, n0 = blockIdx.x * 64;
    const int tx = tid & 15, ty = tid >> 4;
    u64 tot[4][4] = {}, comp[4][4] = {};

    for (int k0 = 0; k0 < DK_; k0 += 16) {
        #pragma unroll
        for (int it = 0; it < 2; it++) {
            int idx = (it << 8) + tid;
            int r = idx >> 2, c = (idx & 3) << 2;
            const float4 a4 = *(const float4*)(qp + (size_t)(m0 + r) * DK_ + k0 + c);
            Qs[c+0][r] = a4.x; Qs[c+1][r] = a4.y; Qs[c+2][r] = a4.z; Qs[c+3][r] = a4.w;
        }
        {
            int r = tid >> 2, c = (tid & 3) << 2;   // r: n-row 0..63, c: k-offset
            const float4 b4 = *(const float4*)(kp + (size_t)(n0 + r) * DK_ + k0 + c);
            Ks[c+0][r] = b4.x; Ks[c+1][r] = b4.y; Ks[c+2][r] = b4.z; Ks[c+3][r] = b4.w;
        }
        __syncthreads();

        u64 cacc[4][4] = {};
        #pragma unroll
        for (int kk = 0; kk < 16; kk++) {
            const ulonglong2* ap = (const ulonglong2*)&Qs[kk][ty*8];
            ulonglong2 p0 = ap[0], p1 = ap[1];
            u64 a0 = p0.x, a1 = p0.y, a2 = p1.x, a3 = p1.y;
            float4 b4 = *(const float4*)&Ks[kk][tx*4];
            u64 b0 = dup2(b4.x), b1 = dup2(b4.y), b2 = dup2(b4.z), b3 = dup2(b4.w);
            f2fma(cacc[0][0], a0, b0); f2fma(cacc[0][1], a0, b1); f2fma(cacc[0][2], a0, b2); f2fma(cacc[0][3], a0, b3);
            f2fma(cacc[1][0], a1, b0); f2fma(cacc[1][1], a1, b1); f2fma(cacc[1][2], a1, b2); f2fma(cacc[1][3], a1, b3);
            f2fma(cacc[2][0], a2, b0); f2fma(cacc[2][1], a2, b1); f2fma(cacc[2][2], a2, b2); f2fma(cacc[2][3], a2, b3);
            f2fma(cacc[3][0], a3, b0); f2fma(cacc[3][1], a3, b1); f2fma(cacc[3][2], a3, b2); f2fma(cacc[3][3], a3, b3);
        }
        #pragma unroll
        for (int i = 0; i < 4; i++)
            #pragma unroll
            for (int j = 0; j < 4; j++)
                ksum2(tot[i][j], comp[i][j], cacc[i][j]);
        __syncthreads();
    }

    const u64 MULT2 = 0x3E2000003E200000ULL;  // (0.15625f, 0.15625f) exact
    float* __restrict__ dst = full ? dst_arg : g_lscratch;
    size_t base = full ? ((size_t)bh * L_ * L_) : 0;
    float res[8][4];
    #pragma unroll
    for (int i = 0; i < 4; i++)
        #pragma unroll
        for (int j = 0; j < 4; j++) {
            u64 r = f2mul(f2add(tot[i][j], comp[i][j]), MULT2);
            unpk2(r, res[2*i][j], res[2*i+1][j]);
        }
    #pragma unroll
    for (int i = 0; i < 8; i++) {
        int m = m0 + ty*8 + i;
        float* rp = dst + base + (size_t)m * L_ + n0 + tx*4;
        *(float4*)rp = make_float4(res[i][0], res[i][1], res[i][2], res[i][3]);
    }
}

// ---------------- top-k v2 (exact 3-pass radix select, measured best) ----------------
__device__ __forceinline__ unsigned fkey(float f) {
    unsigned u = __float_as_uint(f);
    return (u & 0x80000000u) ? ~u : (u | 0x80000000u);  // order-preserving
}

__global__ __launch_bounds__(256) void topk_softmax_kernel(
    float* __restrict__ src_arg, int row0, int write_attn)
{
    __shared__ float row[L_];
    __shared__ unsigned hist[2048];
    __shared__ unsigned wpart[8];
    __shared__ float redf[8];
    __shared__ unsigned s_sel, s_rem;
    __shared__ float s_mx, s_inv;
    __shared__ int s_cnt;

    const int tid = threadIdx.x, lane = tid & 31, wid = tid >> 5;
    float* __restrict__ base = write_attn ? src_arg : g_lscratch;
    float* __restrict__ rptr = base + (size_t)blockIdx.x * L_;
    const int row_id = row0 + blockIdx.x;

    // load row (vectorized) + local max
    float mx = -FLT_MAX;
    #pragma unroll
    for (int i = 0; i < 2; i++) {
        float4 v4 = ((const float4*)rptr)[tid + (i << 8)];
        ((float4*)row)[tid + (i << 8)] = v4;
        mx = fmaxf(fmaxf(fmaxf(mx, v4.x), v4.y), fmaxf(v4.z, v4.w));
    }
    #pragma unroll
    for (int off = 16; off > 0; off >>= 1) mx = fmaxf(mx, __shfl_xor_sync(0xffffffffu, mx, off));
    if (lane == 0) redf[wid] = mx;
    __syncthreads();
    if (tid == 0) {
        float m2 = redf[0];
        #pragma unroll
        for (int w = 1; w < 8; w++) m2 = fmaxf(m2, redf[w]);
        s_mx = m2; s_cnt = 0;
    }

    // exact k-th largest key: 3 radix passes over 11+11+10 bits
    unsigned prefix = 0;
    int rem = TOPK_;
    #pragma unroll
    for (int p = 0; p < 3; p++) {
        const int sh  = (p == 0) ? 21 : (p == 1) ? 10 : 0;
        const int nb  = (p == 2) ? 1024 : 2048;
        const int bpt = nb >> 8;
        const unsigned hm = (p == 0) ? 0u : (p == 1) ? 0xFFE00000u : 0xFFFFFC00u;
        const unsigned bm = (unsigned)nb - 1u;

        for (int j = 0; j < bpt; j++) hist[tid*bpt + j] = 0;
        __syncthreads();
        #pragma unroll
        for (int i = 0; i < 8; i++) {
            unsigned key = fkey(row[tid + (i << 8)]);
            if ((key & hm) == prefix) atomicAdd(&hist[(key >> sh) & bm], 1u);
        }
        __syncthreads();

        // hierarchical inclusive suffix scan over nb bins (descending = larger keys)
        unsigned bsuf[8];
        unsigned tsum = 0;
        for (int j = bpt - 1; j >= 0; j--) { tsum += hist[tid*bpt + j]; bsuf[j] = tsum; }
        unsigned wsuf = tsum;
        #pragma unroll
        for (int off = 1; off < 32; off <<= 1) {
            unsigned o = __shfl_down_sync(0xffffffffu, wsuf, off);
            if (lane + off < 32) wsuf += o;
        }
        if (lane == 0) wpart[wid] = wsuf;   // warp total
        __syncthreads();
        unsigned above = wsuf - tsum;       // lanes strictly above within warp
        for (int w = wid + 1; w < 8; w++) above += wpart[w];

        for (int j = 0; j < bpt; j++) {
            unsigned Si = above + bsuf[j];                                   // count keys with bin >= this
            unsigned own = bsuf[j] - ((j + 1 < bpt) ? bsuf[j+1] : 0u);
            unsigned Se = Si - own;                                          // strictly greater bins
            if ((int)Si >= rem && (int)Se < rem) {
                s_sel = (unsigned)(tid*bpt + j);
                s_rem = (unsigned)(rem - (int)Se);
            }
        }
        __syncthreads();
        prefix |= (s_sel << sh);
        rem = (int)s_rem;
        __syncthreads();
    }
    const unsigned kth = prefix;
    const float mxv = s_mx;

    // exp over kept + sum
    float sm = 0.f;
    #pragma unroll
    for (int i = 0; i < 8; i++) {
        int idx = tid + (i << 8);
        float l = row[idx];
        float e = 0.f;
        if (fkey(l) >= kth) e = expf(l - mxv);
        row[idx] = e;
        sm += e;
    }
    #pragma unroll
    for (int off = 16; off > 0; off >>= 1) sm += __shfl_xor_sync(0xffffffffu, sm, off);
    if (lane == 0) redf[wid] = sm;
    __syncthreads();
    if (tid == 0) {
        float s2 = 0.f;
        #pragma unroll
        for (int w = 0; w < 8; w++) s2 += redf[w];
        s_inv = 1.f / s2;
    }
    __syncthreads();
    const float inv = s_inv;

    // write attn row + compact (idx, p) pairs for sparse PV
    #pragma unroll
    for (int i = 0; i < 2; i++) {
        int vidx = tid + (i << 8);
        float4 e4 = ((float4*)row)[vidx];
        float4 p4 = make_float4(e4.x*inv, e4.y*inv, e4.z*inv, e4.w*inv);
        if (write_attn) ((float4*)rptr)[vidx] = p4;
        int bidx = vidx << 2;
        if (e4.x > 0.f) { int pos = atomicAdd(&s_cnt, 1); if (pos < TOPK_) { g_ti[(size_t)row_id*TOPK_+pos] = bidx+0; g_tp[(size_t)row_id*TOPK_+pos] = p4.x; } }
        if (e4.y > 0.f) { int pos = atomicAdd(&s_cnt, 1); if (pos < TOPK_) { g_ti[(size_t)row_id*TOPK_+pos] = bidx+1; g_tp[(size_t)row_id*TOPK_+pos] = p4.y; } }
        if (e4.z > 0.f) { int pos = atomicAdd(&s_cnt, 1); if (pos < TOPK_) { g_ti[(size_t)row_id*TOPK_+pos] = bidx+2; g_tp[(size_t)row_id*TOPK_+pos] = p4.z; } }
        if (e4.w > 0.f) { int pos = atomicAdd(&s_cnt, 1); if (pos < TOPK_) { g_ti[(size_t)row_id*TOPK_+pos] = bidx+3; g_tp[(size_t)row_id*TOPK_+pos] = p4.w; } }
    }
}

// ---------------- sparse PV: mixed[b][l][h*64+d] = sum over 64 kept keys ----------------
__global__ __launch_bounds__(256) void pv_kernel()
{
    const int row  = blockIdx.x * 8 + (threadIdx.x >> 5);
    const int lane = threadIdx.x & 31;
    const int bh = row >> 11, qi = row & (L_-1);
    const float* __restrict__ vp = g_vp + (size_t)bh * L_ * DV_;
    const int*   __restrict__ ti = g_ti + (size_t)row * TOPK_;
    const float* __restrict__ tp = g_tp + (size_t)row * TOPK_;

    float a0 = 0.f, a1 = 0.f;
    int   i1 = ti[lane];      float p1 = tp[lane];
    int   i2 = ti[32 + lane]; float p2 = tp[32 + lane];
    #pragma unroll
    for (int t = 0; t < 32; t++) {
        int idx = __shfl_sync(0xffffffffu, i1, t);
        float p = __shfl_sync(0xffffffffu, p1, t);
        const float* vr = vp + (size_t)idx * DV_;
        a0 = fmaf(p, vr[lane],      a0);
        a1 = fmaf(p, vr[32 + lane], a1);
    }
    #pragma unroll
    for (int t = 0; t < 32; t++) {
        int idx = __shfl_sync(0xffffffffu, i2, t);
        float p = __shfl_sync(0xffffffffu, p2, t);
        const float* vr = vp + (size_t)idx * DV_;
        a0 = fmaf(p, vr[lane],      a0);
        a1 = fmaf(p, vr[32 + lane], a1);
    }
    const int b = bh >> 4, h = bh & (H_-1);
    float* md = g_mixed + ((size_t)(b * L_ + qi) * (H_*DV_)) + h * DV_;
    md[lane]      = a0;
    md[32 + lane] = a1;
}

// ---------------- fc: out[b*L+l][o] = mixed[row] . fc[:,o] ----------------
__global__ __launch_bounds__(256) void fc_kernel(const float* __restrict__ fcw, float* __restrict__ out)
{
    __shared__ float ms[8][E_];
    const int tid = threadIdx.x;
    const int row0 = blockIdx.x * 8;
    #pragma unroll
    for (int i = 0; i < 8; i++) {
        int idx = (i << 8) + tid;
        ((float4*)&ms[0][0])[idx] = ((const float4*)(g_mixed + (size_t)row0 * E_))[idx];
    }
    __syncthreads();
    const int o = tid & 63, q = tid >> 6;
    float acc0 = 0.f, acc1 = 0.f;
    #pragma unroll 4
    for (int c0 = 0; c0 < E_; c0 += 4) {
        float4 m0 = *(const float4*)&ms[q][c0];
        float4 m1 = *(const float4*)&ms[q + 4][c0];
        float w0 = fcw[(c0+0) * 64 + o];
        float w1 = fcw[(c0+1) * 64 + o];
        float w2 = fcw[(c0+2) * 64 + o];
        float w3 = fcw[(c0+3) * 64 + o];
        acc0 = fmaf(m0.x, w0, acc0); acc0 = fmaf(m0.y, w1, acc0);
        acc0 = fmaf(m0.z, w2, acc0); acc0 = fmaf(m0.w, w3, acc0);
        acc1 = fmaf(m1.x, w0, acc1); acc1 = fmaf(m1.y, w1, acc1);
        acc1 = fmaf(m1.z, w2, acc1); acc1 = fmaf(m1.w, w3, acc1);
    }
    out[(size_t)(row0 + q)     * 64 + o] = acc0;
    out[(size_t)(row0 + q + 4) * 64 + o] = acc1;
}

// ---------------- launcher ----------------
extern "C" void kernel_launch(void* const* d_in, const int* in_sizes, int n_in,
                              void* d_out, int out_size)
{
    const float* q    = (const float*)d_in[0];
    const float* k    = (const float*)d_in[1];
    const float* v    = (const float*)d_in[2];
    const float* w_qs = (const float*)d_in[3];
    const float* w_ks = (const float*)d_in[4];
    const float* w_vs = (const float*)d_in[5];
    const float* fcw  = (const float*)d_in[6];
    float* outp = (float*)d_out;

    const size_t n_out  = (size_t)B_ * L_ * DV_;         // 262144
    const size_t n_attn = (size_t)B_ * H_ * L_ * L_;     // 134217728

    proj_kernel<<<dim3(16, 32, 3), 256>>>(q, k, v, w_qs, w_ks, w_vs);

    bool has_out = false;
    float* attn_ptr = nullptr;
    if ((size_t)out_size == n_out + n_attn) { has_out = true; attn_ptr = outp + n_out; }
    else if ((size_t)out_size == n_attn)    { attn_ptr = outp; }
    else                                    { has_out = true; }

    if (attn_ptr) {
        logits_kernel<<<dim3(32, 16, B_*H_), 256>>>(attn_ptr, 0, 1);
        topk_softmax_kernel<<<NROWS_, 256>>>(attn_ptr, 0, 1);
    } else {
        for (int bh = 0; bh < B_ * H_; bh++) {
            logits_kernel<<<dim3(32, 16, 1), 256>>>(nullptr, bh, 0);
            topk_softmax_kernel<<<L_, 256>>>(nullptr, bh * L_, 0);
        }
    }

    if (has_out) {
        pv_kernel<<<NROWS_/8, 256>>>();
        fc_kernel<<<(B_*L_)/8, 256>>>(fcw, outp);
    }
}